// round 3
// baseline (speedup 1.0000x reference)
#include <cuda_runtime.h>
#include <cstdint>

#define BATCH 4
#define CH    64
#define NPTS  4096
#define KNN   32
#define NOUT  64

// ---------------- device scratch (static: no allocations allowed) ----------------
__device__ float g_sq   [BATCH*NPTS];
__device__ int   g_idx  [BATCH*NPTS*KNN];
__device__ float g_Y1   [BATCH*NPTS*NOUT];
__device__ float g_Y2   [BATCH*NPTS*NOUT];
__device__ float g_hmax [BATCH*NPTS*NOUT];
__device__ float g_hmin [BATCH*NPTS*NOUT];
__device__ float g_Wt1  [CH*NOUT];
__device__ float g_Wt2  [CH*NOUT];
__device__ float g_sum  [NOUT];
__device__ float g_sumsq[NOUT];
__device__ float g_a    [NOUT];
__device__ float g_c    [NOUT];

// ---------------- packed fp32x2 helpers (Blackwell FFMA2) ----------------
__device__ __forceinline__ unsigned long long pack2(float x){
    unsigned long long d; unsigned int xi = __float_as_uint(x);
    asm("mov.b64 %0, {%1, %1};" : "=l"(d) : "r"(xi));
    return d;
}
__device__ __forceinline__ unsigned long long fma2(unsigned long long a,
                                                   unsigned long long b,
                                                   unsigned long long c){
    unsigned long long d;
    asm("fma.rn.f32x2 %0, %1, %2, %3;" : "=l"(d) : "l"(a), "l"(b), "l"(c));
    return d;
}
__device__ __forceinline__ float2 u2f2(unsigned long long u){
    float2 f;
    asm("mov.b64 {%0, %1}, %2;" : "=f"(f.x), "=f"(f.y) : "l"(u));
    return f;
}

// ---------------- kernel 0a: Wt1 = (W1-W2)^T, Wt2 = W2^T ----------------
__global__ void wprep_kernel(const float* __restrict__ W){
    int t = blockIdx.x*256 + threadIdx.x;
    if (t < CH*NOUT){
        int o = t & 63, c = t >> 6;
        float w1 = W[o*2*CH + c];
        float w2 = W[o*2*CH + CH + c];
        g_Wt1[c*NOUT + o] = w1 - w2;
        g_Wt2[c*NOUT + o] = w2;
    }
}

// ---------------- kernel 0b: squared norms ----------------
__global__ void sqnorm_kernel(const float* __restrict__ points){
    int t = blockIdx.x*256 + threadIdx.x;         // 0..16383
    int b = t >> 12, n = t & (NPTS-1);
    const float* P = points + b*CH*NPTS + n;
    float s = 0.f;
    #pragma unroll
    for (int c = 0; c < CH; ++c){ float v = __ldg(P + c*NPTS); s = fmaf(v, v, s); }
    g_sq[t] = s;
}

// ---------------- kernel 0c: zero BN accumulators (graph replays!) ----------------
__global__ void zero_kernel(){
    int t = threadIdx.x;
    if (t < NOUT){ g_sum[t] = 0.f; g_sumsq[t] = 0.f; }
}

// ---------------- kernel 1: fused distance GEMM + top-32 selection ----------------
// grid = BATCH*32 blocks, 256 threads. Block owns 128 query points; streams
// all 4096 candidates in chunks of 128. Key = sq_m - 2*dot (minimize).
// Dynamic smem: Qs(32K) + Cs(32K) + Sc(64K) + Tv(16K) + Ti(16K) = 160KB.
__global__ void __launch_bounds__(256, 1) knn_kernel(const float* __restrict__ points){
    extern __shared__ float sm[];
    float* Qs = sm;                   // [64][128]
    float* Cs = Qs + 64*128;          // [64][128]
    float* Sc = Cs + 64*128;          // [128][128] scores
    float* Tv = Sc + 128*128;         // [128][32] top-k values (sorted asc per row)
    int*   Ti = (int*)(Tv + 128*KNN); // [128][32] top-k indices

    const int tid  = threadIdx.x;
    const int lane = tid & 31;
    const int wid  = tid >> 5;
    const int b     = blockIdx.x >> 5;
    const int qbase = (blockIdx.x & 31) * 128;
    const float* P = points + b*CH*NPTS;

    for (int t = tid; t < 128*KNN; t += 256){ Tv[t] = 3.0e38f; Ti[t] = 0; }

    // load query tile Qs[c][i]
    #pragma unroll
    for (int it = 0; it < 8; ++it){
        int idx = it*256 + tid;
        int c = idx >> 5, i4 = idx & 31;
        float4 v = __ldg(reinterpret_cast<const float4*>(P + c*NPTS + qbase) + i4);
        reinterpret_cast<float4*>(Qs + c*128)[i4] = v;
    }

    const int q0 = (tid >> 4) * 8;   // query row base (8 rows)
    const int m0 = (tid & 15) * 8;   // candidate col base (8 cols)

    #pragma unroll 1
    for (int chunk = 0; chunk < NPTS/128; ++chunk){
        const int mbase = chunk * 128;
        __syncthreads();   // selection of previous chunk done before Cs reload
        #pragma unroll
        for (int it = 0; it < 8; ++it){
            int idx = it*256 + tid;
            int c = idx >> 5, i4 = idx & 31;
            float4 v = __ldg(reinterpret_cast<const float4*>(P + c*NPTS + mbase) + i4);
            reinterpret_cast<float4*>(Cs + c*128)[i4] = v;
        }
        __syncthreads();

        // 8x8 register-tile GEMM with packed f32x2 FMAs (acc pairs along m)
        unsigned long long acc[8][4];
        #pragma unroll
        for (int j = 0; j < 8; ++j)
            #pragma unroll
            for (int p = 0; p < 4; ++p) acc[j][p] = 0ull;

        #pragma unroll 8
        for (int c = 0; c < CH; ++c){
            float4 a0 = *reinterpret_cast<const float4*>(Qs + c*128 + q0);
            float4 a1 = *reinterpret_cast<const float4*>(Qs + c*128 + q0 + 4);
            ulonglong2 b0 = *reinterpret_cast<const ulonglong2*>(Cs + c*128 + m0);
            ulonglong2 b1 = *reinterpret_cast<const ulonglong2*>(Cs + c*128 + m0 + 4);
            unsigned long long bp0 = b0.x, bp1 = b0.y, bp2 = b1.x, bp3 = b1.y;
            float af[8] = {a0.x,a0.y,a0.z,a0.w,a1.x,a1.y,a1.z,a1.w};
            #pragma unroll
            for (int j = 0; j < 8; ++j){
                unsigned long long aj = pack2(af[j]);
                acc[j][0] = fma2(aj, bp0, acc[j][0]);
                acc[j][1] = fma2(aj, bp1, acc[j][1]);
                acc[j][2] = fma2(aj, bp2, acc[j][2]);
                acc[j][3] = fma2(aj, bp3, acc[j][3]);
            }
        }

        float sqc[8];
        #pragma unroll
        for (int jj = 0; jj < 8; ++jj)
            sqc[jj] = __ldg(&g_sq[b*NPTS + mbase + m0 + jj]);

        #pragma unroll
        for (int j = 0; j < 8; ++j){
            float2 f0 = u2f2(acc[j][0]), f1 = u2f2(acc[j][1]);
            float2 f2 = u2f2(acc[j][2]), f3 = u2f2(acc[j][3]);
            float4 r0, r1;
            r0.x = sqc[0] - 2.f*f0.x;  r0.y = sqc[1] - 2.f*f0.y;
            r0.z = sqc[2] - 2.f*f1.x;  r0.w = sqc[3] - 2.f*f1.y;
            r1.x = sqc[4] - 2.f*f2.x;  r1.y = sqc[5] - 2.f*f2.y;
            r1.z = sqc[6] - 2.f*f3.x;  r1.w = sqc[7] - 2.f*f3.y;
            *reinterpret_cast<float4*>(Sc + (q0+j)*128 + m0)     = r0;
            *reinterpret_cast<float4*>(Sc + (q0+j)*128 + m0 + 4) = r1;
        }
        __syncthreads();

        // top-k update: warp `wid` owns queries [wid*16, wid*16+16)
        #pragma unroll 1
        for (int qq = 0; qq < 16; ++qq){
            const int q = wid*16 + qq;
            float thr = Tv[q*KNN + 31];              // broadcast LDS
            const float* row = Sc + q*128;
            #pragma unroll 1
            for (int sub = 0; sub < 4; ++sub){
                float s = row[sub*32 + lane];
                if (__any_sync(0xffffffffu, s < thr)){
                    int si = mbase + sub*32 + lane;
                    // bitonic sort (s,si) ascending across the warp
                    #pragma unroll
                    for (int k = 2; k <= 32; k <<= 1){
                        #pragma unroll
                        for (int j = k>>1; j > 0; j >>= 1){
                            float ov = __shfl_xor_sync(0xffffffffu, s, j);
                            int   oi = __shfl_xor_sync(0xffffffffu, si, j);
                            bool keep_small = (((lane & j) == 0) == ((lane & k) == 0));
                            bool take = keep_small ? (ov < s) : (ov > s);
                            if (take){ s = ov; si = oi; }
                        }
                    }
                    // merge with current sorted-asc list, keep 32 smallest
                    float v  = Tv[q*KNN + lane];
                    int   vi = Ti[q*KNN + lane];
                    float rs = __shfl_sync(0xffffffffu, s, 31 - lane);
                    int   ri = __shfl_sync(0xffffffffu, si, 31 - lane);
                    if (rs < v){ v = rs; vi = ri; }
                    #pragma unroll
                    for (int j = 16; j > 0; j >>= 1){
                        float ov = __shfl_xor_sync(0xffffffffu, v, j);
                        int   oi = __shfl_xor_sync(0xffffffffu, vi, j);
                        bool keep_small = ((lane & j) == 0);
                        bool take = keep_small ? (ov < v) : (ov > v);
                        if (take){ v = ov; vi = oi; }
                    }
                    Tv[q*KNN + lane] = v;
                    Ti[q*KNN + lane] = vi;
                    thr = __shfl_sync(0xffffffffu, v, 31);
                }
            }
        }
    }

    // write neighbor indices (each lane wrote its own slot; same-thread RAW)
    #pragma unroll
    for (int qq = 0; qq < 16; ++qq){
        int q = wid*16 + qq;
        g_idx[(b*NPTS + qbase + q)*KNN + lane] = Ti[q*KNN + lane];
    }
}

// ---------------- kernel 2: Y1 = X*(W1-W2)^T, Y2 = X*W2^T ----------------
// grid = BATCH*32, 256 threads, dynamic smem 64KB
__global__ void __launch_bounds__(256, 1) ygemm_kernel(const float* __restrict__ points){
    extern __shared__ float sm[];
    float* Xs  = sm;            // [64][128]
    float* W1s = Xs + 64*128;   // [64][64]
    float* W2s = W1s + 64*64;   // [64][64]

    const int tid = threadIdx.x;
    const int b = blockIdx.x >> 5;
    const int nbase = (blockIdx.x & 31) * 128;
    const float* P = points + b*CH*NPTS;

    #pragma unroll
    for (int it = 0; it < 8; ++it){
        int idx = it*256 + tid;
        int c = idx >> 5, i4 = idx & 31;
        reinterpret_cast<float4*>(Xs + c*128)[i4] =
            __ldg(reinterpret_cast<const float4*>(P + c*NPTS + nbase) + i4);
    }
    #pragma unroll
    for (int it = 0; it < 4; ++it){
        int idx = it*256 + tid;
        reinterpret_cast<float4*>(W1s)[idx] = __ldg(reinterpret_cast<const float4*>(g_Wt1) + idx);
        reinterpret_cast<float4*>(W2s)[idx] = __ldg(reinterpret_cast<const float4*>(g_Wt2) + idx);
    }
    __syncthreads();

    const int n0 = (tid & 31) * 4;
    const int o0 = (tid >> 5) * 8;
    float acc1[4][8], acc2[4][8];
    #pragma unroll
    for (int j = 0; j < 4; ++j)
        #pragma unroll
        for (int r = 0; r < 8; ++r){ acc1[j][r] = 0.f; acc2[j][r] = 0.f; }

    #pragma unroll 8
    for (int c = 0; c < CH; ++c){
        float4 a   = *reinterpret_cast<const float4*>(Xs  + c*128 + n0);
        float4 w10 = *reinterpret_cast<const float4*>(W1s + c*64 + o0);
        float4 w11 = *reinterpret_cast<const float4*>(W1s + c*64 + o0 + 4);
        float4 w20 = *reinterpret_cast<const float4*>(W2s + c*64 + o0);
        float4 w21 = *reinterpret_cast<const float4*>(W2s + c*64 + o0 + 4);
        float af[4]  = {a.x, a.y, a.z, a.w};
        float w1f[8] = {w10.x,w10.y,w10.z,w10.w,w11.x,w11.y,w11.z,w11.w};
        float w2f[8] = {w20.x,w20.y,w20.z,w20.w,w21.x,w21.y,w21.z,w21.w};
        #pragma unroll
        for (int j = 0; j < 4; ++j)
            #pragma unroll
            for (int r = 0; r < 8; ++r){
                acc1[j][r] = fmaf(af[j], w1f[r], acc1[j][r]);
                acc2[j][r] = fmaf(af[j], w2f[r], acc2[j][r]);
            }
    }

    #pragma unroll
    for (int j = 0; j < 4; ++j){
        int row = (b*NPTS + nbase + n0 + j)*NOUT + o0;
        float4 u0 = make_float4(acc1[j][0],acc1[j][1],acc1[j][2],acc1[j][3]);
        float4 u1 = make_float4(acc1[j][4],acc1[j][5],acc1[j][6],acc1[j][7]);
        float4 v0 = make_float4(acc2[j][0],acc2[j][1],acc2[j][2],acc2[j][3]);
        float4 v1 = make_float4(acc2[j][4],acc2[j][5],acc2[j][6],acc2[j][7]);
        *reinterpret_cast<float4*>(g_Y1 + row)     = u0;
        *reinterpret_cast<float4*>(g_Y1 + row + 4) = u1;
        *reinterpret_cast<float4*>(g_Y2 + row)     = v0;
        *reinterpret_cast<float4*>(g_Y2 + row + 4) = v1;
    }
}

// ---------------- kernel 3: gather neighbors, h stats, per-(n,o) max/min over k ----------------
// grid = BATCH*32 blocks of 256. Warp handles 2 points; 16 lanes x float4 cover 64 channels.
__global__ void __launch_bounds__(256, 1) gather_kernel(){
    __shared__ float ssum[NOUT], ssum2[NOUT];
    const int tid = threadIdx.x;
    if (tid < NOUT){ ssum[tid] = 0.f; ssum2[tid] = 0.f; }
    __syncthreads();

    const int b = blockIdx.x >> 5;
    const int nbase = (blockIdx.x & 31) * 128;
    const int lane = tid & 31, wid = tid >> 5;
    const int half = lane >> 4;
    const int c4 = lane & 15;

    const float4* Y1f = reinterpret_cast<const float4*>(g_Y1);
    const float4* Y2f = reinterpret_cast<const float4*>(g_Y2);
    float4* hmaxf = reinterpret_cast<float4*>(g_hmax);
    float4* hminf = reinterpret_cast<float4*>(g_hmin);

    float a0=0.f, a1=0.f, a2=0.f, a3=0.f;      // sum h
    float b0=0.f, b1=0.f, b2=0.f, b3=0.f;      // sum h^2

    #pragma unroll 1
    for (int it = 0; it < 8; ++it){
        int np  = nbase + it*16 + wid*2;
        int bnp = b*NPTS + np;
        int ia = g_idx[ bnp   *KNN + lane];
        int ib = g_idx[(bnp+1)*KNN + lane];
        int bn = bnp + half;
        float4 y1 = __ldg(Y1f + bn*16 + c4);
        float4 mx = make_float4(-3.0e38f,-3.0e38f,-3.0e38f,-3.0e38f);
        float4 mn = make_float4( 3.0e38f, 3.0e38f, 3.0e38f, 3.0e38f);
        #pragma unroll
        for (int k = 0; k < KNN; ++k){
            int ma = __shfl_sync(0xffffffffu, ia, k);
            int mb = __shfl_sync(0xffffffffu, ib, k);
            int m  = half ? mb : ma;
            float4 y2 = __ldg(Y2f + (b*NPTS + m)*16 + c4);
            float h0 = y1.x + y2.x, h1 = y1.y + y2.y, h2 = y1.z + y2.z, h3 = y1.w + y2.w;
            a0 += h0; a1 += h1; a2 += h2; a3 += h3;
            b0 = fmaf(h0,h0,b0); b1 = fmaf(h1,h1,b1); b2 = fmaf(h2,h2,b2); b3 = fmaf(h3,h3,b3);
            mx.x = fmaxf(mx.x,h0); mx.y = fmaxf(mx.y,h1); mx.z = fmaxf(mx.z,h2); mx.w = fmaxf(mx.w,h3);
            mn.x = fminf(mn.x,h0); mn.y = fminf(mn.y,h1); mn.z = fminf(mn.z,h2); mn.w = fminf(mn.w,h3);
        }
        hmaxf[bn*16 + c4] = mx;
        hminf[bn*16 + c4] = mn;
    }

    atomicAdd(&ssum [c4*4+0], a0); atomicAdd(&ssum [c4*4+1], a1);
    atomicAdd(&ssum [c4*4+2], a2); atomicAdd(&ssum [c4*4+3], a3);
    atomicAdd(&ssum2[c4*4+0], b0); atomicAdd(&ssum2[c4*4+1], b1);
    atomicAdd(&ssum2[c4*4+2], b2); atomicAdd(&ssum2[c4*4+3], b3);
    __syncthreads();
    if (tid < NOUT){
        atomicAdd(&g_sum[tid],   ssum[tid]);
        atomicAdd(&g_sumsq[tid], ssum2[tid]);
    }
}

// ---------------- kernel 4: BN scale/shift ----------------
__global__ void finalize_kernel(const float* __restrict__ gamma,
                                const float* __restrict__ beta){
    int o = threadIdx.x;
    if (o < NOUT){
        const float inv = 1.f / (float)(BATCH*NPTS*KNN);
        float mean = g_sum[o] * inv;
        float var  = g_sumsq[o] * inv - mean*mean;
        float a = gamma[o] * rsqrtf(var + 1e-5f);
        g_a[o] = a;
        g_c[o] = beta[o] - a*mean;
    }
}

// ---------------- kernel 5: affine + relu + transpose to (B,O,N) ----------------
// max_k relu(a*h+c) = relu(a*h* + c), h* = hmax if a>=0 else hmin
__global__ void __launch_bounds__(256, 1) output_kernel(float* __restrict__ out){
    __shared__ float smx[64][65];
    __shared__ float smn[64][65];
    const int tid = threadIdx.x;
    const int b = blockIdx.x >> 6;
    const int nbase = (blockIdx.x & 63) * 64;
    const float4* hmaxf = reinterpret_cast<const float4*>(g_hmax);
    const float4* hminf = reinterpret_cast<const float4*>(g_hmin);

    #pragma unroll
    for (int it = 0; it < 4; ++it){
        int idx = it*256 + tid;              // 0..1023
        int r = idx >> 4, cc = idx & 15;
        float4 v = __ldg(hmaxf + (b*NPTS + nbase + r)*16 + cc);
        smx[r][cc*4+0] = v.x; smx[r][cc*4+1] = v.y; smx[r][cc*4+2] = v.z; smx[r][cc*4+3] = v.w;
        float4 w = __ldg(hminf + (b*NPTS + nbase + r)*16 + cc);
        smn[r][cc*4+0] = w.x; smn[r][cc*4+1] = w.y; smn[r][cc*4+2] = w.z; smn[r][cc*4+3] = w.w;
    }
    __syncthreads();

    #pragma unroll
    for (int it = 0; it < 16; ++it){
        int o  = it*4 + (tid >> 6);
        int nn = tid & 63;
        float a = g_a[o], c = g_c[o];
        float h = (a >= 0.f) ? smx[nn][o] : smn[nn][o];
        out[b*NOUT*NPTS + o*NPTS + nbase + nn] = fmaxf(fmaf(a, h, c), 0.f);
    }
}

// ---------------- launch ----------------
extern "C" void kernel_launch(void* const* d_in, const int* in_sizes, int n_in,
                              void* d_out, int out_size){
    const float* points = (const float*)d_in[0];   // (B, C, N)
    const float* W      = (const float*)d_in[1];   // (O, 2C)
    const float* gamma  = (const float*)d_in[2];   // (O,)
    const float* beta   = (const float*)d_in[3];   // (O,)
    float* out = (float*)d_out;                    // (B, O, N)

    cudaFuncSetAttribute((const void*)knn_kernel,
                         cudaFuncAttributeMaxDynamicSharedMemorySize, 160*1024);
    cudaFuncSetAttribute((const void*)ygemm_kernel,
                         cudaFuncAttributeMaxDynamicSharedMemorySize, 64*1024);

    wprep_kernel  <<<16, 256>>>(W);
    sqnorm_kernel <<<64, 256>>>(points);
    zero_kernel   <<<1, 64>>>();
    knn_kernel    <<<BATCH*(NPTS/128), 256, 160*1024>>>(points);
    ygemm_kernel  <<<BATCH*(NPTS/128), 256, 64*1024>>>(points);
    gather_kernel <<<BATCH*(NPTS/128), 256>>>();
    finalize_kernel<<<1, 64>>>(gamma, beta);
    output_kernel <<<BATCH*(NPTS/64), 256>>>(out);
}

// round 4
// speedup vs baseline: 1.9278x; 1.9278x over previous
#include <cuda_runtime.h>
#include <cstdint>

#define BATCH 4
#define CH    64
#define NPTS  4096
#define KNN   32
#define NOUT  64

// ---------------- device scratch (static: no allocations allowed) ----------------
__device__ float g_sq   [BATCH*NPTS];
__device__ int   g_idx  [BATCH*NPTS*KNN];
__device__ float g_Y1   [BATCH*NPTS*NOUT];
__device__ float g_Y2   [BATCH*NPTS*NOUT];
__device__ float g_hmax [BATCH*NPTS*NOUT];
__device__ float g_hmin [BATCH*NPTS*NOUT];
__device__ float g_Wt1  [CH*NOUT];
__device__ float g_Wt2  [CH*NOUT];
__device__ float g_sum  [NOUT];
__device__ float g_sumsq[NOUT];
__device__ float g_a    [NOUT];
__device__ float g_c    [NOUT];

// ---------------- packed fp32x2 helpers (Blackwell FFMA2) ----------------
__device__ __forceinline__ unsigned long long pack2(float x){
    unsigned long long d; unsigned int xi = __float_as_uint(x);
    asm("mov.b64 %0, {%1, %1};" : "=l"(d) : "r"(xi));
    return d;
}
__device__ __forceinline__ unsigned long long fma2(unsigned long long a,
                                                   unsigned long long b,
                                                   unsigned long long c){
    unsigned long long d;
    asm("fma.rn.f32x2 %0, %1, %2, %3;" : "=l"(d) : "l"(a), "l"(b), "l"(c));
    return d;
}
__device__ __forceinline__ float2 u2f2(unsigned long long u){
    float2 f;
    asm("mov.b64 {%0, %1}, %2;" : "=f"(f.x), "=f"(f.y) : "l"(u));
    return f;
}

// ---------------- kernel 0a: Wt1 = (W1-W2)^T, Wt2 = W2^T ----------------
__global__ void wprep_kernel(const float* __restrict__ W){
    int t = blockIdx.x*256 + threadIdx.x;
    if (t < CH*NOUT){
        int o = t & 63, c = t >> 6;
        float w1 = W[o*2*CH + c];
        float w2 = W[o*2*CH + CH + c];
        g_Wt1[c*NOUT + o] = w1 - w2;
        g_Wt2[c*NOUT + o] = w2;
    }
}

// ---------------- kernel 0b: squared norms ----------------
__global__ void sqnorm_kernel(const float* __restrict__ points){
    int t = blockIdx.x*256 + threadIdx.x;         // 0..16383
    int b = t >> 12, n = t & (NPTS-1);
    const float* P = points + b*CH*NPTS + n;
    float s = 0.f;
    #pragma unroll
    for (int c = 0; c < CH; ++c){ float v = __ldg(P + c*NPTS); s = fmaf(v, v, s); }
    g_sq[t] = s;
}

// ---------------- kernel 0c: zero BN accumulators (graph replays!) ----------------
__global__ void zero_kernel(){
    int t = threadIdx.x;
    if (t < NOUT){ g_sum[t] = 0.f; g_sumsq[t] = 0.f; }
}

// ---------------- per-thread 32-entry max-heap in smem (stride 256) ----------------
// keys: (monotonic_u32(score) << 32) | candidate_index.  Root = slot 0 = max.
// replace root with `key` (must be < root), sift down, return new root's hi-32.
__device__ __forceinline__ unsigned int heap_replace(unsigned long long* H, int tid,
                                                     unsigned long long key){
    int i = 0;
    #pragma unroll 5
    for (int lvl = 0; lvl < 5; ++lvl){
        int l = 2*i + 1;
        if (l > 31) break;
        unsigned long long c = H[(l<<8) + tid];
        int ci = l;
        if (l < 31){
            unsigned long long c2 = H[((l+1)<<8) + tid];
            if (c2 > c){ c = c2; ci = l + 1; }
        }
        if (c > key){ H[(i<<8) + tid] = c; i = ci; }
        else break;
    }
    H[(i<<8) + tid] = key;
    return (unsigned int)(H[tid] >> 32);
}

__device__ __forceinline__ unsigned int mono_key(unsigned int bits){
    return bits ^ (unsigned int)(((int)bits >> 31) | 0x80000000);
}

// ---------------- kernel 1: fused distance GEMM + per-thread heap top-32 ----------------
// grid = BATCH*32 blocks, 256 threads. Block owns 128 queries; streams 4096
// candidates in chunks of 128. Score = sq_m - 2*dot (minimize; ranking-equivalent
// to reference neg_dist). Each thread owns one (query, candidate-half) stream.
// smem: Qs 32K + Cs 32K + Sc[128][132] 66K + heaps[32][256] 64K = 194KB.
__global__ void __launch_bounds__(256, 1) knn_kernel(const float* __restrict__ points){
    extern __shared__ float sm[];
    float* Qs = sm;                         // [64][128]
    float* Cs = Qs + 64*128;                // [64][128]
    float* Sc = Cs + 64*128;                // [128][132] (padded rows)
    unsigned long long* H = reinterpret_cast<unsigned long long*>(Sc + 128*132); // [32][256]

    const int tid  = threadIdx.x;
    const int lane = tid & 31;
    const int wid  = tid >> 5;
    const int b     = blockIdx.x >> 5;
    const int qbase = (blockIdx.x & 31) * 128;
    const float* P = points + b*CH*NPTS;

    // init heaps with +inf keys (replace-root path fills them naturally)
    #pragma unroll
    for (int s = 0; s < 32; ++s) H[(s<<8) + tid] = ~0ull;
    unsigned int thr_hi = 0xFFFFFFFFu;

    // load query tile Qs[c][i]
    #pragma unroll
    for (int it = 0; it < 8; ++it){
        int idx = it*256 + tid;
        int c = idx >> 5, i4 = idx & 31;
        reinterpret_cast<float4*>(Qs + c*128)[i4] =
            __ldg(reinterpret_cast<const float4*>(P + c*NPTS + qbase) + i4);
    }

    const int q0 = wid * 16;     // 16 queries per warp (GEMM tile)
    const int m0 = lane * 4;     // 4 candidates per lane
    const int myq = tid >> 1;    // selection: thread owns one query...
    const int myh = tid & 1;     // ...and one half (64 candidates/chunk)
    const unsigned int* myrow = reinterpret_cast<const unsigned int*>(Sc + myq*132 + myh*64);

    #pragma unroll 1
    for (int chunk = 0; chunk < NPTS/128; ++chunk){
        const int mbase = chunk * 128;
        // load candidate tile Cs[c][i]
        #pragma unroll
        for (int it = 0; it < 8; ++it){
            int idx = it*256 + tid;
            int c = idx >> 5, i4 = idx & 31;
            reinterpret_cast<float4*>(Cs + c*128)[i4] =
                __ldg(reinterpret_cast<const float4*>(P + c*NPTS + mbase) + i4);
        }
        __syncthreads();   // Cs ready; also: prev-chunk scan done before Sc overwrite

        // 16q x 4m register tile; f32x2 pairs along q (no packs on q side)
        unsigned long long acc[8][4];
        #pragma unroll
        for (int qp = 0; qp < 8; ++qp)
            #pragma unroll
            for (int j = 0; j < 4; ++j) acc[qp][j] = 0ull;

        #pragma unroll 8
        for (int c = 0; c < CH; ++c){
            const float* qrow = Qs + c*128 + q0;
            ulonglong2 qv0 = *reinterpret_cast<const ulonglong2*>(qrow);
            ulonglong2 qv1 = *reinterpret_cast<const ulonglong2*>(qrow + 4);
            ulonglong2 qv2 = *reinterpret_cast<const ulonglong2*>(qrow + 8);
            ulonglong2 qv3 = *reinterpret_cast<const ulonglong2*>(qrow + 12);
            float4 cv = *reinterpret_cast<const float4*>(Cs + c*128 + m0);
            unsigned long long bp0 = pack2(cv.x), bp1 = pack2(cv.y),
                               bp2 = pack2(cv.z), bp3 = pack2(cv.w);
            unsigned long long ap[8] = {qv0.x,qv0.y,qv1.x,qv1.y,qv2.x,qv2.y,qv3.x,qv3.y};
            #pragma unroll
            for (int qp = 0; qp < 8; ++qp){
                acc[qp][0] = fma2(ap[qp], bp0, acc[qp][0]);
                acc[qp][1] = fma2(ap[qp], bp1, acc[qp][1]);
                acc[qp][2] = fma2(ap[qp], bp2, acc[qp][2]);
                acc[qp][3] = fma2(ap[qp], bp3, acc[qp][3]);
            }
        }

        float4 sqv = __ldg(reinterpret_cast<const float4*>(g_sq + b*NPTS + mbase + m0));
        #pragma unroll
        for (int qp = 0; qp < 8; ++qp){
            float2 d0 = u2f2(acc[qp][0]), d1 = u2f2(acc[qp][1]);
            float2 d2 = u2f2(acc[qp][2]), d3 = u2f2(acc[qp][3]);
            float4 se = make_float4(fmaf(-2.f,d0.x,sqv.x), fmaf(-2.f,d1.x,sqv.y),
                                    fmaf(-2.f,d2.x,sqv.z), fmaf(-2.f,d3.x,sqv.w));
            float4 so = make_float4(fmaf(-2.f,d0.y,sqv.x), fmaf(-2.f,d1.y,sqv.y),
                                    fmaf(-2.f,d2.y,sqv.z), fmaf(-2.f,d3.y,sqv.w));
            *reinterpret_cast<float4*>(Sc + (q0 + 2*qp    )*132 + m0) = se;
            *reinterpret_cast<float4*>(Sc + (q0 + 2*qp + 1)*132 + m0) = so;
        }
        __syncthreads();   // Sc ready for scan

        // scan my 64 candidates, scalar heap inserts (no shuffles)
        const int gbase = mbase + myh*64;
        #pragma unroll 1
        for (int i = 0; i < 16; ++i){
            uint4 w = *reinterpret_cast<const uint4*>(myrow + i*4);
            unsigned int mk;
            mk = mono_key(w.x);
            if (mk < thr_hi)
                thr_hi = heap_replace(H, tid, ((unsigned long long)mk<<32) | (unsigned)(gbase + i*4 + 0));
            mk = mono_key(w.y);
            if (mk < thr_hi)
                thr_hi = heap_replace(H, tid, ((unsigned long long)mk<<32) | (unsigned)(gbase + i*4 + 1));
            mk = mono_key(w.z);
            if (mk < thr_hi)
                thr_hi = heap_replace(H, tid, ((unsigned long long)mk<<32) | (unsigned)(gbase + i*4 + 2));
            mk = mono_key(w.w);
            if (mk < thr_hi)
                thr_hi = heap_replace(H, tid, ((unsigned long long)mk<<32) | (unsigned)(gbase + i*4 + 3));
        }
        __syncthreads();   // scan done before next chunk's Sc overwrite
    }

    // merge partner half's heap into half-0 heap (exact), then write indices
    if (myh == 0){
        #pragma unroll 1
        for (int s = 0; s < 32; ++s){
            unsigned long long k = H[(s<<8) + tid + 1];
            if ((unsigned int)(k >> 32) < thr_hi)
                thr_hi = heap_replace(H, tid, k);
        }
        int base = (b*NPTS + qbase + myq)*KNN;
        #pragma unroll
        for (int s = 0; s < 32; ++s)
            g_idx[base + s] = (int)(unsigned int)H[(s<<8) + tid];
    }
}

// ---------------- kernel 2: Y1 = X*(W1-W2)^T, Y2 = X*W2^T ----------------
__global__ void __launch_bounds__(256, 1) ygemm_kernel(const float* __restrict__ points){
    extern __shared__ float sm[];
    float* Xs  = sm;            // [64][128]
    float* W1s = Xs + 64*128;   // [64][64]
    float* W2s = W1s + 64*64;   // [64][64]

    const int tid = threadIdx.x;
    const int b = blockIdx.x >> 5;
    const int nbase = (blockIdx.x & 31) * 128;
    const float* P = points + b*CH*NPTS;

    #pragma unroll
    for (int it = 0; it < 8; ++it){
        int idx = it*256 + tid;
        int c = idx >> 5, i4 = idx & 31;
        reinterpret_cast<float4*>(Xs + c*128)[i4] =
            __ldg(reinterpret_cast<const float4*>(P + c*NPTS + nbase) + i4);
    }
    #pragma unroll
    for (int it = 0; it < 4; ++it){
        int idx = it*256 + tid;
        reinterpret_cast<float4*>(W1s)[idx] = __ldg(reinterpret_cast<const float4*>(g_Wt1) + idx);
        reinterpret_cast<float4*>(W2s)[idx] = __ldg(reinterpret_cast<const float4*>(g_Wt2) + idx);
    }
    __syncthreads();

    const int n0 = (tid & 31) * 4;
    const int o0 = (tid >> 5) * 8;
    float acc1[4][8], acc2[4][8];
    #pragma unroll
    for (int j = 0; j < 4; ++j)
        #pragma unroll
        for (int r = 0; r < 8; ++r){ acc1[j][r] = 0.f; acc2[j][r] = 0.f; }

    #pragma unroll 8
    for (int c = 0; c < CH; ++c){
        float4 a   = *reinterpret_cast<const float4*>(Xs  + c*128 + n0);
        float4 w10 = *reinterpret_cast<const float4*>(W1s + c*64 + o0);
        float4 w11 = *reinterpret_cast<const float4*>(W1s + c*64 + o0 + 4);
        float4 w20 = *reinterpret_cast<const float4*>(W2s + c*64 + o0);
        float4 w21 = *reinterpret_cast<const float4*>(W2s + c*64 + o0 + 4);
        float af[4]  = {a.x, a.y, a.z, a.w};
        float w1f[8] = {w10.x,w10.y,w10.z,w10.w,w11.x,w11.y,w11.z,w11.w};
        float w2f[8] = {w20.x,w20.y,w20.z,w20.w,w21.x,w21.y,w21.z,w21.w};
        #pragma unroll
        for (int j = 0; j < 4; ++j)
            #pragma unroll
            for (int r = 0; r < 8; ++r){
                acc1[j][r] = fmaf(af[j], w1f[r], acc1[j][r]);
                acc2[j][r] = fmaf(af[j], w2f[r], acc2[j][r]);
            }
    }

    #pragma unroll
    for (int j = 0; j < 4; ++j){
        int row = (b*NPTS + nbase + n0 + j)*NOUT + o0;
        *reinterpret_cast<float4*>(g_Y1 + row)     = make_float4(acc1[j][0],acc1[j][1],acc1[j][2],acc1[j][3]);
        *reinterpret_cast<float4*>(g_Y1 + row + 4) = make_float4(acc1[j][4],acc1[j][5],acc1[j][6],acc1[j][7]);
        *reinterpret_cast<float4*>(g_Y2 + row)     = make_float4(acc2[j][0],acc2[j][1],acc2[j][2],acc2[j][3]);
        *reinterpret_cast<float4*>(g_Y2 + row + 4) = make_float4(acc2[j][4],acc2[j][5],acc2[j][6],acc2[j][7]);
    }
}

// ---------------- kernel 3: gather neighbors, h stats, per-(n,o) max/min over k ----------------
// grid = BATCH*64 blocks of 256. Warp handles 2 points; 16 lanes x float4 = 64 channels.
__global__ void __launch_bounds__(256, 1) gather_kernel(){
    __shared__ float ssum[NOUT], ssum2[NOUT];
    const int tid = threadIdx.x;
    if (tid < NOUT){ ssum[tid] = 0.f; ssum2[tid] = 0.f; }
    __syncthreads();

    const int b = blockIdx.x >> 6;
    const int nbase = (blockIdx.x & 63) * 64;
    const int lane = tid & 31, wid = tid >> 5;
    const int half = lane >> 4;
    const int c4 = lane & 15;

    const float4* Y1f = reinterpret_cast<const float4*>(g_Y1);
    const float4* Y2f = reinterpret_cast<const float4*>(g_Y2);
    float4* hmaxf = reinterpret_cast<float4*>(g_hmax);
    float4* hminf = reinterpret_cast<float4*>(g_hmin);

    float a0=0.f, a1=0.f, a2=0.f, a3=0.f;
    float b0=0.f, b1=0.f, b2=0.f, b3=0.f;

    #pragma unroll 1
    for (int it = 0; it < 4; ++it){
        int np  = nbase + it*16 + wid*2;
        int bnp = b*NPTS + np;
        int ia = g_idx[ bnp   *KNN + lane];
        int ib = g_idx[(bnp+1)*KNN + lane];
        int bn = bnp + half;
        float4 y1 = __ldg(Y1f + bn*16 + c4);
        float4 mx = make_float4(-3.0e38f,-3.0e38f,-3.0e38f,-3.0e38f);
        float4 mn = make_float4( 3.0e38f, 3.0e38f, 3.0e38f, 3.0e38f);
        #pragma unroll
        for (int k = 0; k < KNN; ++k){
            int ma = __shfl_sync(0xffffffffu, ia, k);
            int mb = __shfl_sync(0xffffffffu, ib, k);
            int m  = half ? mb : ma;
            float4 y2 = __ldg(Y2f + (b*NPTS + m)*16 + c4);
            float h0 = y1.x + y2.x, h1 = y1.y + y2.y, h2 = y1.z + y2.z, h3 = y1.w + y2.w;
            a0 += h0; a1 += h1; a2 += h2; a3 += h3;
            b0 = fmaf(h0,h0,b0); b1 = fmaf(h1,h1,b1); b2 = fmaf(h2,h2,b2); b3 = fmaf(h3,h3,b3);
            mx.x = fmaxf(mx.x,h0); mx.y = fmaxf(mx.y,h1); mx.z = fmaxf(mx.z,h2); mx.w = fmaxf(mx.w,h3);
            mn.x = fminf(mn.x,h0); mn.y = fminf(mn.y,h1); mn.z = fminf(mn.z,h2); mn.w = fminf(mn.w,h3);
        }
        hmaxf[bn*16 + c4] = mx;
        hminf[bn*16 + c4] = mn;
    }

    atomicAdd(&ssum [c4*4+0], a0); atomicAdd(&ssum [c4*4+1], a1);
    atomicAdd(&ssum [c4*4+2], a2); atomicAdd(&ssum [c4*4+3], a3);
    atomicAdd(&ssum2[c4*4+0], b0); atomicAdd(&ssum2[c4*4+1], b1);
    atomicAdd(&ssum2[c4*4+2], b2); atomicAdd(&ssum2[c4*4+3], b3);
    __syncthreads();
    if (tid < NOUT){
        atomicAdd(&g_sum[tid],   ssum[tid]);
        atomicAdd(&g_sumsq[tid], ssum2[tid]);
    }
}

// ---------------- kernel 4: BN scale/shift ----------------
__global__ void finalize_kernel(const float* __restrict__ gamma,
                                const float* __restrict__ beta){
    int o = threadIdx.x;
    if (o < NOUT){
        const float inv = 1.f / (float)(BATCH*NPTS*KNN);
        float mean = g_sum[o] * inv;
        float var  = g_sumsq[o] * inv - mean*mean;
        float a = gamma[o] * rsqrtf(var + 1e-5f);
        g_a[o] = a;
        g_c[o] = beta[o] - a*mean;
    }
}

// ---------------- kernel 5: affine + relu + transpose to (B,O,N) ----------------
__global__ void __launch_bounds__(256, 1) output_kernel(float* __restrict__ out){
    __shared__ float smx[64][65];
    __shared__ float smn[64][65];
    const int tid = threadIdx.x;
    const int b = blockIdx.x >> 6;
    const int nbase = (blockIdx.x & 63) * 64;
    const float4* hmaxf = reinterpret_cast<const float4*>(g_hmax);
    const float4* hminf = reinterpret_cast<const float4*>(g_hmin);

    #pragma unroll
    for (int it = 0; it < 4; ++it){
        int idx = it*256 + tid;
        int r = idx >> 4, cc = idx & 15;
        float4 v = __ldg(hmaxf + (b*NPTS + nbase + r)*16 + cc);
        smx[r][cc*4+0] = v.x; smx[r][cc*4+1] = v.y; smx[r][cc*4+2] = v.z; smx[r][cc*4+3] = v.w;
        float4 w = __ldg(hminf + (b*NPTS + nbase + r)*16 + cc);
        smn[r][cc*4+0] = w.x; smn[r][cc*4+1] = w.y; smn[r][cc*4+2] = w.z; smn[r][cc*4+3] = w.w;
    }
    __syncthreads();

    #pragma unroll
    for (int it = 0; it < 16; ++it){
        int o  = it*4 + (tid >> 6);
        int nn = tid & 63;
        float a = g_a[o], c = g_c[o];
        float h = (a >= 0.f) ? smx[nn][o] : smn[nn][o];
        out[b*NOUT*NPTS + o*NPTS + nbase + nn] = fmaxf(fmaf(a, h, c), 0.f);
    }
}

// ---------------- launch ----------------
extern "C" void kernel_launch(void* const* d_in, const int* in_sizes, int n_in,
                              void* d_out, int out_size){
    const float* points = (const float*)d_in[0];   // (B, C, N)
    const float* W      = (const float*)d_in[1];   // (O, 2C)
    const float* gamma  = (const float*)d_in[2];   // (O,)
    const float* beta   = (const float*)d_in[3];   // (O,)
    float* out = (float*)d_out;                    // (B, O, N)

    const int KNN_SMEM = (64*128 + 64*128 + 128*132)*4 + 32*256*8;  // 198656 B
    cudaFuncSetAttribute((const void*)knn_kernel,
                         cudaFuncAttributeMaxDynamicSharedMemorySize, KNN_SMEM);
    cudaFuncSetAttribute((const void*)ygemm_kernel,
                         cudaFuncAttributeMaxDynamicSharedMemorySize, 64*1024);

    wprep_kernel   <<<16, 256>>>(W);
    sqnorm_kernel  <<<64, 256>>>(points);
    zero_kernel    <<<1, 64>>>();
    knn_kernel     <<<BATCH*(NPTS/128), 256, KNN_SMEM>>>(points);
    ygemm_kernel   <<<BATCH*(NPTS/128), 256, 64*1024>>>(points);
    gather_kernel  <<<BATCH*(NPTS/64), 256>>>();
    finalize_kernel<<<1, 64>>>(gamma, beta);
    output_kernel  <<<BATCH*(NPTS/64), 256>>>(out);
}

// round 5
// speedup vs baseline: 2.8436x; 1.4750x over previous
#include <cuda_runtime.h>
#include <cstdint>

#define BATCH 4
#define CH    64
#define NPTS  4096
#define KNN   32
#define NOUT  64

// ---------------- device scratch (static: no allocations allowed) ----------------
__device__ float g_sq   [BATCH*NPTS];
__device__ int   g_idx  [BATCH*NPTS*KNN];
__device__ float g_Y1   [BATCH*NPTS*NOUT];
__device__ float g_Y2   [BATCH*NPTS*NOUT];
__device__ float g_hmax [BATCH*NPTS*NOUT];
__device__ float g_hmin [BATCH*NPTS*NOUT];
__device__ float g_Wt1  [CH*NOUT];
__device__ float g_Wt2  [CH*NOUT];
__device__ float g_sum  [NOUT];
__device__ float g_sumsq[NOUT];
__device__ float g_a    [NOUT];
__device__ float g_c    [NOUT];

// ---------------- packed fp32x2 helpers (Blackwell FFMA2) ----------------
__device__ __forceinline__ unsigned long long pack2(float x){
    unsigned long long d; unsigned int xi = __float_as_uint(x);
    asm("mov.b64 %0, {%1, %1};" : "=l"(d) : "r"(xi));
    return d;
}
__device__ __forceinline__ unsigned long long fma2(unsigned long long a,
                                                   unsigned long long b,
                                                   unsigned long long c){
    unsigned long long d;
    asm("fma.rn.f32x2 %0, %1, %2, %3;" : "=l"(d) : "l"(a), "l"(b), "l"(c));
    return d;
}
__device__ __forceinline__ float2 u2f2(unsigned long long u){
    float2 f;
    asm("mov.b64 {%0, %1}, %2;" : "=f"(f.x), "=f"(f.y) : "l"(u));
    return f;
}

// ---------------- kernel 0a: Wt1 = (W1-W2)^T, Wt2 = W2^T ----------------
__global__ void wprep_kernel(const float* __restrict__ W){
    int t = blockIdx.x*256 + threadIdx.x;
    if (t < CH*NOUT){
        int o = t & 63, c = t >> 6;
        float w1 = W[o*2*CH + c];
        float w2 = W[o*2*CH + CH + c];
        g_Wt1[c*NOUT + o] = w1 - w2;
        g_Wt2[c*NOUT + o] = w2;
    }
}

// ---------------- kernel 0b: squared norms ----------------
__global__ void sqnorm_kernel(const float* __restrict__ points){
    int t = blockIdx.x*256 + threadIdx.x;         // 0..16383
    int b = t >> 12, n = t & (NPTS-1);
    const float* P = points + b*CH*NPTS + n;
    float s = 0.f;
    #pragma unroll
    for (int c = 0; c < CH; ++c){ float v = __ldg(P + c*NPTS); s = fmaf(v, v, s); }
    g_sq[t] = s;
}

// ---------------- kernel 0c: zero BN accumulators (graph replays!) ----------------
__global__ void zero_kernel(){
    int t = threadIdx.x;
    if (t < NOUT){ g_sum[t] = 0.f; g_sumsq[t] = 0.f; }
}

// ---------------- kernel 1: fused distance GEMM + register top-32 ----------------
// grid = BATCH*32 blocks x 512 threads (16 warps). Block owns 128 queries;
// warp w owns queries [8w, 8w+8). Streams 4096 candidates in chunks of 128;
// each lane computes scores for its 8 queries x 4 candidates (m = 4*lane..).
// Per (warp,query) top-32 kept as a sorted-ascending list, one entry per lane,
// updated with ballot + shfl_up shift inserts. Score = sq_m - 2*dot
// (rank-equivalent to reference neg_dist).
// smem: Qs[64][128] 32K + Cs[64][128] 32K + Ss[4096] 16K = 80KB.
__global__ void __launch_bounds__(512, 1) knn_kernel(const float* __restrict__ points){
    extern __shared__ float sm[];
    float* Qs = sm;               // [64][128]
    float* Cs = Qs + 64*128;      // [64][128]
    float* Ss = Cs + 64*128;      // [4096] candidate sq-norms

    const int tid  = threadIdx.x;
    const int lane = tid & 31;
    const int wid  = tid >> 5;
    const int b     = blockIdx.x >> 5;
    const int qbase = (blockIdx.x & 31) * 128;
    const float* P = points + b*CH*NPTS;

    // load query tile Qs[c][i]  (2048 float4, 512 threads -> 4 each)
    #pragma unroll
    for (int it = 0; it < 4; ++it){
        int idx = it*512 + tid;
        int c = idx >> 5, i4 = idx & 31;
        reinterpret_cast<float4*>(Qs + c*128)[i4] =
            __ldg(reinterpret_cast<const float4*>(P + c*NPTS + qbase) + i4);
    }
    // load sq-norm cache (1024 float4 -> 2 each)
    #pragma unroll
    for (int it = 0; it < 2; ++it){
        int idx = it*512 + tid;
        reinterpret_cast<float4*>(Ss)[idx] =
            __ldg(reinterpret_cast<const float4*>(g_sq + b*NPTS) + idx);
    }

    // per-(warp,query) sorted list: lane l holds l-th smallest
    float Lv[8]; int Li[8];
    #pragma unroll
    for (int qi = 0; qi < 8; ++qi){ Lv[qi] = 3.0e38f; Li[qi] = 0; }
    float thr[8];
    #pragma unroll
    for (int qi = 0; qi < 8; ++qi) thr[qi] = 3.0e38f;

    const int q0 = wid * 8;      // this warp's first query
    const int m0 = lane * 4;     // this lane's candidate base within chunk

    #pragma unroll 1
    for (int chunk = 0; chunk < NPTS/128; ++chunk){
        const int mbase = chunk * 128;
        __syncthreads();   // all warps done reading previous Cs
        #pragma unroll
        for (int it = 0; it < 4; ++it){
            int idx = it*512 + tid;
            int c = idx >> 5, i4 = idx & 31;
            reinterpret_cast<float4*>(Cs + c*128)[i4] =
                __ldg(reinterpret_cast<const float4*>(P + c*NPTS + mbase) + i4);
        }
        __syncthreads();

        // GEMM: 8 queries (4 f32x2 pairs) x 4 candidates per lane
        unsigned long long acc[4][4];
        #pragma unroll
        for (int p = 0; p < 4; ++p)
            #pragma unroll
            for (int j = 0; j < 4; ++j) acc[p][j] = 0ull;

        #pragma unroll 8
        for (int c = 0; c < CH; ++c){
            const float* qrow = Qs + c*128 + q0;
            ulonglong2 qv0 = *reinterpret_cast<const ulonglong2*>(qrow);      // q0..q3
            ulonglong2 qv1 = *reinterpret_cast<const ulonglong2*>(qrow + 4);  // q4..q7
            float4 cv = *reinterpret_cast<const float4*>(Cs + c*128 + m0);
            unsigned long long bp0 = pack2(cv.x), bp1 = pack2(cv.y),
                               bp2 = pack2(cv.z), bp3 = pack2(cv.w);
            unsigned long long ap[4] = {qv0.x, qv0.y, qv1.x, qv1.y};
            #pragma unroll
            for (int p = 0; p < 4; ++p){
                acc[p][0] = fma2(ap[p], bp0, acc[p][0]);
                acc[p][1] = fma2(ap[p], bp1, acc[p][1]);
                acc[p][2] = fma2(ap[p], bp2, acc[p][2]);
                acc[p][3] = fma2(ap[p], bp3, acc[p][3]);
            }
        }

        float4 sqv = *reinterpret_cast<const float4*>(Ss + mbase + m0);
        float sc[8][4];
        #pragma unroll
        for (int p = 0; p < 4; ++p){
            float2 d0 = u2f2(acc[p][0]), d1 = u2f2(acc[p][1]);
            float2 d2 = u2f2(acc[p][2]), d3 = u2f2(acc[p][3]);
            sc[2*p  ][0] = fmaf(-2.f, d0.x, sqv.x);
            sc[2*p  ][1] = fmaf(-2.f, d1.x, sqv.y);
            sc[2*p  ][2] = fmaf(-2.f, d2.x, sqv.z);
            sc[2*p  ][3] = fmaf(-2.f, d3.x, sqv.w);
            sc[2*p+1][0] = fmaf(-2.f, d0.y, sqv.x);
            sc[2*p+1][1] = fmaf(-2.f, d1.y, sqv.y);
            sc[2*p+1][2] = fmaf(-2.f, d2.y, sqv.z);
            sc[2*p+1][3] = fmaf(-2.f, d3.y, sqv.w);
        }

        // selection: ballot-filtered shfl-shift inserts (no smem, no divergence)
        #pragma unroll
        for (int qi = 0; qi < 8; ++qi){
            #pragma unroll
            for (int j = 0; j < 4; ++j){
                float sj = sc[qi][j];
                unsigned mask = __ballot_sync(0xffffffffu, sj < thr[qi]);
                while (mask){
                    int src = __ffs(mask) - 1;
                    mask &= mask - 1;
                    float v = __shfl_sync(0xffffffffu, sj, src);
                    int gi = mbase + src*4 + j;
                    // insertion position: after any equal values (lower index wins ties)
                    int pos = __popc(__ballot_sync(0xffffffffu, Lv[qi] <= v));
                    float upv = __shfl_up_sync(0xffffffffu, Lv[qi], 1);
                    int   upi = __shfl_up_sync(0xffffffffu, Li[qi], 1);
                    if (lane == pos){ Lv[qi] = v; Li[qi] = gi; }
                    else if (lane > pos){ Lv[qi] = upv; Li[qi] = upi; }
                    thr[qi] = __shfl_sync(0xffffffffu, Lv[qi], 31);
                    mask &= __ballot_sync(0xffffffffu, sj < thr[qi]);
                }
            }
        }
    }

    // write indices: lane l holds l-th nearest of each owned query
    #pragma unroll
    for (int qi = 0; qi < 8; ++qi)
        g_idx[(b*NPTS + qbase + q0 + qi)*KNN + lane] = Li[qi];
}

// ---------------- kernel 2: Y1 = X*(W1-W2)^T, Y2 = X*W2^T ----------------
__global__ void __launch_bounds__(256, 1) ygemm_kernel(const float* __restrict__ points){
    extern __shared__ float sm[];
    float* Xs  = sm;            // [64][128]
    float* W1s = Xs + 64*128;   // [64][64]
    float* W2s = W1s + 64*64;   // [64][64]

    const int tid = threadIdx.x;
    const int b = blockIdx.x >> 5;
    const int nbase = (blockIdx.x & 31) * 128;
    const float* P = points + b*CH*NPTS;

    #pragma unroll
    for (int it = 0; it < 8; ++it){
        int idx = it*256 + tid;
        int c = idx >> 5, i4 = idx & 31;
        reinterpret_cast<float4*>(Xs + c*128)[i4] =
            __ldg(reinterpret_cast<const float4*>(P + c*NPTS + nbase) + i4);
    }
    #pragma unroll
    for (int it = 0; it < 4; ++it){
        int idx = it*256 + tid;
        reinterpret_cast<float4*>(W1s)[idx] = __ldg(reinterpret_cast<const float4*>(g_Wt1) + idx);
        reinterpret_cast<float4*>(W2s)[idx] = __ldg(reinterpret_cast<const float4*>(g_Wt2) + idx);
    }
    __syncthreads();

    const int n0 = (tid & 31) * 4;
    const int o0 = (tid >> 5) * 8;
    float acc1[4][8], acc2[4][8];
    #pragma unroll
    for (int j = 0; j < 4; ++j)
        #pragma unroll
        for (int r = 0; r < 8; ++r){ acc1[j][r] = 0.f; acc2[j][r] = 0.f; }

    #pragma unroll 8
    for (int c = 0; c < CH; ++c){
        float4 a   = *reinterpret_cast<const float4*>(Xs  + c*128 + n0);
        float4 w10 = *reinterpret_cast<const float4*>(W1s + c*64 + o0);
        float4 w11 = *reinterpret_cast<const float4*>(W1s + c*64 + o0 + 4);
        float4 w20 = *reinterpret_cast<const float4*>(W2s + c*64 + o0);
        float4 w21 = *reinterpret_cast<const float4*>(W2s + c*64 + o0 + 4);
        float af[4]  = {a.x, a.y, a.z, a.w};
        float w1f[8] = {w10.x,w10.y,w10.z,w10.w,w11.x,w11.y,w11.z,w11.w};
        float w2f[8] = {w20.x,w20.y,w20.z,w20.w,w21.x,w21.y,w21.z,w21.w};
        #pragma unroll
        for (int j = 0; j < 4; ++j)
            #pragma unroll
            for (int r = 0; r < 8; ++r){
                acc1[j][r] = fmaf(af[j], w1f[r], acc1[j][r]);
                acc2[j][r] = fmaf(af[j], w2f[r], acc2[j][r]);
            }
    }

    #pragma unroll
    for (int j = 0; j < 4; ++j){
        int row = (b*NPTS + nbase + n0 + j)*NOUT + o0;
        *reinterpret_cast<float4*>(g_Y1 + row)     = make_float4(acc1[j][0],acc1[j][1],acc1[j][2],acc1[j][3]);
        *reinterpret_cast<float4*>(g_Y1 + row + 4) = make_float4(acc1[j][4],acc1[j][5],acc1[j][6],acc1[j][7]);
        *reinterpret_cast<float4*>(g_Y2 + row)     = make_float4(acc2[j][0],acc2[j][1],acc2[j][2],acc2[j][3]);
        *reinterpret_cast<float4*>(g_Y2 + row + 4) = make_float4(acc2[j][4],acc2[j][5],acc2[j][6],acc2[j][7]);
    }
}

// ---------------- kernel 3: gather neighbors, h stats, per-(n,o) max/min over k ----------------
__global__ void __launch_bounds__(256, 1) gather_kernel(){
    __shared__ float ssum[NOUT], ssum2[NOUT];
    const int tid = threadIdx.x;
    if (tid < NOUT){ ssum[tid] = 0.f; ssum2[tid] = 0.f; }
    __syncthreads();

    const int b = blockIdx.x >> 6;
    const int nbase = (blockIdx.x & 63) * 64;
    const int lane = tid & 31, wid = tid >> 5;
    const int half = lane >> 4;
    const int c4 = lane & 15;

    const float4* Y1f = reinterpret_cast<const float4*>(g_Y1);
    const float4* Y2f = reinterpret_cast<const float4*>(g_Y2);
    float4* hmaxf = reinterpret_cast<float4*>(g_hmax);
    float4* hminf = reinterpret_cast<float4*>(g_hmin);

    float a0=0.f, a1=0.f, a2=0.f, a3=0.f;
    float b0=0.f, b1=0.f, b2=0.f, b3=0.f;

    #pragma unroll 1
    for (int it = 0; it < 4; ++it){
        int np  = nbase + it*16 + wid*2;
        int bnp = b*NPTS + np;
        int ia = g_idx[ bnp   *KNN + lane];
        int ib = g_idx[(bnp+1)*KNN + lane];
        int bn = bnp + half;
        float4 y1 = __ldg(Y1f + bn*16 + c4);
        float4 mx = make_float4(-3.0e38f,-3.0e38f,-3.0e38f,-3.0e38f);
        float4 mn = make_float4( 3.0e38f, 3.0e38f, 3.0e38f, 3.0e38f);
        #pragma unroll
        for (int k = 0; k < KNN; ++k){
            int ma = __shfl_sync(0xffffffffu, ia, k);
            int mb = __shfl_sync(0xffffffffu, ib, k);
            int m  = half ? mb : ma;
            float4 y2 = __ldg(Y2f + (b*NPTS + m)*16 + c4);
            float h0 = y1.x + y2.x, h1 = y1.y + y2.y, h2 = y1.z + y2.z, h3 = y1.w + y2.w;
            a0 += h0; a1 += h1; a2 += h2; a3 += h3;
            b0 = fmaf(h0,h0,b0); b1 = fmaf(h1,h1,b1); b2 = fmaf(h2,h2,b2); b3 = fmaf(h3,h3,b3);
            mx.x = fmaxf(mx.x,h0); mx.y = fmaxf(mx.y,h1); mx.z = fmaxf(mx.z,h2); mx.w = fmaxf(mx.w,h3);
            mn.x = fminf(mn.x,h0); mn.y = fminf(mn.y,h1); mn.z = fminf(mn.z,h2); mn.w = fminf(mn.w,h3);
        }
        hmaxf[bn*16 + c4] = mx;
        hminf[bn*16 + c4] = mn;
    }

    atomicAdd(&ssum [c4*4+0], a0); atomicAdd(&ssum [c4*4+1], a1);
    atomicAdd(&ssum [c4*4+2], a2); atomicAdd(&ssum [c4*4+3], a3);
    atomicAdd(&ssum2[c4*4+0], b0); atomicAdd(&ssum2[c4*4+1], b1);
    atomicAdd(&ssum2[c4*4+2], b2); atomicAdd(&ssum2[c4*4+3], b3);
    __syncthreads();
    if (tid < NOUT){
        atomicAdd(&g_sum[tid],   ssum[tid]);
        atomicAdd(&g_sumsq[tid], ssum2[tid]);
    }
}

// ---------------- kernel 4: BN scale/shift ----------------
__global__ void finalize_kernel(const float* __restrict__ gamma,
                                const float* __restrict__ beta){
    int o = threadIdx.x;
    if (o < NOUT){
        const float inv = 1.f / (float)(BATCH*NPTS*KNN);
        float mean = g_sum[o] * inv;
        float var  = g_sumsq[o] * inv - mean*mean;
        float a = gamma[o] * rsqrtf(var + 1e-5f);
        g_a[o] = a;
        g_c[o] = beta[o] - a*mean;
    }
}

// ---------------- kernel 5: affine + relu + transpose to (B,O,N) ----------------
__global__ void __launch_bounds__(256, 1) output_kernel(float* __restrict__ out){
    __shared__ float smx[64][65];
    __shared__ float smn[64][65];
    const int tid = threadIdx.x;
    const int b = blockIdx.x >> 6;
    const int nbase = (blockIdx.x & 63) * 64;
    const float4* hmaxf = reinterpret_cast<const float4*>(g_hmax);
    const float4* hminf = reinterpret_cast<const float4*>(g_hmin);

    #pragma unroll
    for (int it = 0; it < 4; ++it){
        int idx = it*256 + tid;
        int r = idx >> 4, cc = idx & 15;
        float4 v = __ldg(hmaxf + (b*NPTS + nbase + r)*16 + cc);
        smx[r][cc*4+0] = v.x; smx[r][cc*4+1] = v.y; smx[r][cc*4+2] = v.z; smx[r][cc*4+3] = v.w;
        float4 w = __ldg(hminf + (b*NPTS + nbase + r)*16 + cc);
        smn[r][cc*4+0] = w.x; smn[r][cc*4+1] = w.y; smn[r][cc*4+2] = w.z; smn[r][cc*4+3] = w.w;
    }
    __syncthreads();

    #pragma unroll
    for (int it = 0; it < 16; ++it){
        int o  = it*4 + (tid >> 6);
        int nn = tid & 63;
        float a = g_a[o], c = g_c[o];
        float h = (a >= 0.f) ? smx[nn][o] : smn[nn][o];
        out[b*NOUT*NPTS + o*NPTS + nbase + nn] = fmaxf(fmaf(a, h, c), 0.f);
    }
}

// ---------------- launch ----------------
extern "C" void kernel_launch(void* const* d_in, const int* in_sizes, int n_in,
                              void* d_out, int out_size){
    const float* points = (const float*)d_in[0];   // (B, C, N)
    const float* W      = (const float*)d_in[1];   // (O, 2C)
    const float* gamma  = (const float*)d_in[2];   // (O,)
    const float* beta   = (const float*)d_in[3];   // (O,)
    float* out = (float*)d_out;                    // (B, O, N)

    const int KNN_SMEM = (64*128 + 64*128 + 4096) * 4;   // 81920 B
    cudaFuncSetAttribute((const void*)knn_kernel,
                         cudaFuncAttributeMaxDynamicSharedMemorySize, KNN_SMEM);
    cudaFuncSetAttribute((const void*)ygemm_kernel,
                         cudaFuncAttributeMaxDynamicSharedMemorySize, 64*1024);

    wprep_kernel   <<<16, 256>>>(W);
    sqnorm_kernel  <<<64, 256>>>(points);
    zero_kernel    <<<1, 64>>>();
    knn_kernel     <<<BATCH*(NPTS/128), 512, KNN_SMEM>>>(points);
    ygemm_kernel   <<<BATCH*(NPTS/128), 256, 64*1024>>>(points);
    gather_kernel  <<<BATCH*(NPTS/64), 256>>>();
    finalize_kernel<<<1, 64>>>(gamma, beta);
    output_kernel  <<<BATCH*(NPTS/64), 256>>>(out);
}

// round 6
// speedup vs baseline: 3.1425x; 1.1051x over previous
#include <cuda_runtime.h>
#include <cstdint>

#define BATCH 4
#define CH    64
#define NPTS  4096
#define KNN   32
#define NOUT  64

// ---------------- device scratch (static: no allocations allowed) ----------------
__device__ float g_sq   [BATCH*NPTS];
__device__ int   g_idx  [BATCH*NPTS*KNN];
__device__ float g_Y1   [BATCH*NPTS*NOUT];
__device__ float g_Y2   [BATCH*NPTS*NOUT];
__device__ float g_hmax [BATCH*NPTS*NOUT];
__device__ float g_hmin [BATCH*NPTS*NOUT];
__device__ float g_Wt1  [CH*NOUT];
__device__ float g_Wt2  [CH*NOUT];
__device__ float g_sum  [NOUT];
__device__ float g_sumsq[NOUT];
__device__ float g_a    [NOUT];
__device__ float g_c    [NOUT];

// ---------------- packed fp32x2 helpers (Blackwell FFMA2) ----------------
__device__ __forceinline__ unsigned long long pack2(float x){
    unsigned long long d; unsigned int xi = __float_as_uint(x);
    asm("mov.b64 %0, {%1, %1};" : "=l"(d) : "r"(xi));
    return d;
}
__device__ __forceinline__ unsigned long long fma2(unsigned long long a,
                                                   unsigned long long b,
                                                   unsigned long long c){
    unsigned long long d;
    asm("fma.rn.f32x2 %0, %1, %2, %3;" : "=l"(d) : "l"(a), "l"(b), "l"(c));
    return d;
}
__device__ __forceinline__ float2 u2f2(unsigned long long u){
    float2 f;
    asm("mov.b64 {%0, %1}, %2;" : "=f"(f.x), "=f"(f.y) : "l"(u));
    return f;
}

// ---------------- kernel 0a: Wt1 = (W1-W2)^T, Wt2 = W2^T ----------------
__global__ void wprep_kernel(const float* __restrict__ W){
    int t = blockIdx.x*256 + threadIdx.x;
    if (t < CH*NOUT){
        int o = t & 63, c = t >> 6;
        float w1 = W[o*2*CH + c];
        float w2 = W[o*2*CH + CH + c];
        g_Wt1[c*NOUT + o] = w1 - w2;
        g_Wt2[c*NOUT + o] = w2;
    }
}

// ---------------- kernel 0b: squared norms ----------------
__global__ void sqnorm_kernel(const float* __restrict__ points){
    int t = blockIdx.x*256 + threadIdx.x;         // 0..16383
    int b = t >> 12, n = t & (NPTS-1);
    const float* P = points + b*CH*NPTS + n;
    float s = 0.f;
    #pragma unroll
    for (int c = 0; c < CH; ++c){ float v = __ldg(P + c*NPTS); s = fmaf(v, v, s); }
    g_sq[t] = s;
}

// ---------------- kernel 0c: zero BN accumulators (graph replays!) ----------------
__global__ void zero_kernel(){
    int t = threadIdx.x;
    if (t < NOUT){ g_sum[t] = 0.f; g_sumsq[t] = 0.f; }
}

// ---------------- kernel 1: fused distance GEMM + register top-32 ----------------
// grid = BATCH*64 blocks x 512 threads (16 warps), 2 blocks/SM (64 regs).
// Block owns 64 queries; warp w owns queries [4w, 4w+4). Streams 4096
// candidates in chunks of 128; each lane scores 4 queries x 4 candidates.
// Cs holds -2*x; acc initialized to sq_m, so score = sq_m - 2*dot directly.
// Per (warp,query) top-32 kept as sorted-ascending list, one entry per lane,
// ballot + shfl_up shift inserts, with a per-query min-prefilter.
// smem: Qs[64][64] 16K + Cs[64][128] 32K + Ss[4096] 16K = 64KB.
__global__ void __launch_bounds__(512, 2) knn_kernel(const float* __restrict__ points){
    extern __shared__ float sm[];
    float* Qs = sm;               // [64][64]
    float* Cs = Qs + 64*64;       // [64][128]  (pre-scaled by -2)
    float* Ss = Cs + 64*128;      // [4096] candidate sq-norms

    const int tid  = threadIdx.x;
    const int lane = tid & 31;
    const int wid  = tid >> 5;
    const int b     = blockIdx.x >> 6;
    const int qbase = (blockIdx.x & 63) * 64;
    const float* P = points + b*CH*NPTS;

    // load query tile Qs[c][i]  (1024 float4, 512 threads -> 2 each)
    #pragma unroll
    for (int it = 0; it < 2; ++it){
        int idx = it*512 + tid;
        int c = idx >> 4, i4 = idx & 15;
        reinterpret_cast<float4*>(Qs + c*64)[i4] =
            __ldg(reinterpret_cast<const float4*>(P + c*NPTS + qbase) + i4);
    }
    // load sq-norm cache (1024 float4 -> 2 each)
    #pragma unroll
    for (int it = 0; it < 2; ++it){
        int idx = it*512 + tid;
        reinterpret_cast<float4*>(Ss)[idx] =
            __ldg(reinterpret_cast<const float4*>(g_sq + b*NPTS) + idx);
    }

    // per-(warp,query) sorted list: lane l holds l-th smallest
    float Lv[4]; int Li[4]; float thr[4];
    #pragma unroll
    for (int qi = 0; qi < 4; ++qi){ Lv[qi] = 3.0e38f; Li[qi] = 0; thr[qi] = 3.0e38f; }

    const int q0 = wid * 4;      // this warp's first query (broadcast smem reads)
    const int m0 = lane * 4;     // this lane's candidate base within chunk

    #pragma unroll 1
    for (int chunk = 0; chunk < NPTS/128; ++chunk){
        const int mbase = chunk * 128;
        __syncthreads();   // all warps done reading previous Cs
        // fill Cs with -2 * x  (2048 float4 -> 4 each)
        #pragma unroll
        for (int it = 0; it < 4; ++it){
            int idx = it*512 + tid;
            int c = idx >> 5, i4 = idx & 31;
            float4 v = __ldg(reinterpret_cast<const float4*>(P + c*NPTS + mbase) + i4);
            v.x *= -2.f; v.y *= -2.f; v.z *= -2.f; v.w *= -2.f;
            reinterpret_cast<float4*>(Cs + c*128)[i4] = v;
        }
        __syncthreads();

        // acc init = sq of candidates (same for both queries in each pair)
        float4 sqv = *reinterpret_cast<const float4*>(Ss + mbase + m0);
        unsigned long long acc[2][4];
        acc[0][0] = acc[1][0] = pack2(sqv.x);
        acc[0][1] = acc[1][1] = pack2(sqv.y);
        acc[0][2] = acc[1][2] = pack2(sqv.z);
        acc[0][3] = acc[1][3] = pack2(sqv.w);

        // GEMM: 4 queries (2 f32x2 pairs) x 4 candidates per lane
        #pragma unroll 4
        for (int c = 0; c < CH; ++c){
            ulonglong2 qv = *reinterpret_cast<const ulonglong2*>(Qs + c*64 + q0); // bcast
            float4 cv = *reinterpret_cast<const float4*>(Cs + c*128 + m0);
            unsigned long long bp0 = pack2(cv.x), bp1 = pack2(cv.y),
                               bp2 = pack2(cv.z), bp3 = pack2(cv.w);
            acc[0][0] = fma2(qv.x, bp0, acc[0][0]);
            acc[0][1] = fma2(qv.x, bp1, acc[0][1]);
            acc[0][2] = fma2(qv.x, bp2, acc[0][2]);
            acc[0][3] = fma2(qv.x, bp3, acc[0][3]);
            acc[1][0] = fma2(qv.y, bp0, acc[1][0]);
            acc[1][1] = fma2(qv.y, bp1, acc[1][1]);
            acc[1][2] = fma2(qv.y, bp2, acc[1][2]);
            acc[1][3] = fma2(qv.y, bp3, acc[1][3]);
        }

        // unpack scores: sc[qi][j]
        float sc[4][4];
        #pragma unroll
        for (int p = 0; p < 2; ++p){
            float2 d0 = u2f2(acc[p][0]), d1 = u2f2(acc[p][1]);
            float2 d2 = u2f2(acc[p][2]), d3 = u2f2(acc[p][3]);
            sc[2*p  ][0] = d0.x; sc[2*p  ][1] = d1.x; sc[2*p  ][2] = d2.x; sc[2*p  ][3] = d3.x;
            sc[2*p+1][0] = d0.y; sc[2*p+1][1] = d1.y; sc[2*p+1][2] = d2.y; sc[2*p+1][3] = d3.y;
        }

        // selection with per-query min-prefilter
        #pragma unroll
        for (int qi = 0; qi < 4; ++qi){
            float mn = fminf(fminf(sc[qi][0], sc[qi][1]), fminf(sc[qi][2], sc[qi][3]));
            if (!__any_sync(0xffffffffu, mn < thr[qi])) continue;
            #pragma unroll
            for (int j = 0; j < 4; ++j){
                float sj = sc[qi][j];
                unsigned mask = __ballot_sync(0xffffffffu, sj < thr[qi]);
                while (mask){
                    int src = __ffs(mask) - 1;
                    mask &= mask - 1;
                    float v = __shfl_sync(0xffffffffu, sj, src);
                    int gi = mbase + src*4 + j;
                    int pos = __popc(__ballot_sync(0xffffffffu, Lv[qi] <= v));
                    float upv = __shfl_up_sync(0xffffffffu, Lv[qi], 1);
                    int   upi = __shfl_up_sync(0xffffffffu, Li[qi], 1);
                    if (lane == pos){ Lv[qi] = v; Li[qi] = gi; }
                    else if (lane > pos){ Lv[qi] = upv; Li[qi] = upi; }
                    thr[qi] = __shfl_sync(0xffffffffu, Lv[qi], 31);
                    mask &= __ballot_sync(0xffffffffu, sj < thr[qi]);
                }
            }
        }
    }

    // write indices: lane l holds l-th nearest of each owned query
    #pragma unroll
    for (int qi = 0; qi < 4; ++qi)
        g_idx[(b*NPTS + qbase + q0 + qi)*KNN + lane] = Li[qi];
}

// ---------------- kernel 2: Y1 = X*(W1-W2)^T, Y2 = X*W2^T ----------------
__global__ void __launch_bounds__(256, 1) ygemm_kernel(const float* __restrict__ points){
    extern __shared__ float sm[];
    float* Xs  = sm;            // [64][128]
    float* W1s = Xs + 64*128;   // [64][64]
    float* W2s = W1s + 64*64;   // [64][64]

    const int tid = threadIdx.x;
    const int b = blockIdx.x >> 5;
    const int nbase = (blockIdx.x & 31) * 128;
    const float* P = points + b*CH*NPTS;

    #pragma unroll
    for (int it = 0; it < 8; ++it){
        int idx = it*256 + tid;
        int c = idx >> 5, i4 = idx & 31;
        reinterpret_cast<float4*>(Xs + c*128)[i4] =
            __ldg(reinterpret_cast<const float4*>(P + c*NPTS + nbase) + i4);
    }
    #pragma unroll
    for (int it = 0; it < 4; ++it){
        int idx = it*256 + tid;
        reinterpret_cast<float4*>(W1s)[idx] = __ldg(reinterpret_cast<const float4*>(g_Wt1) + idx);
        reinterpret_cast<float4*>(W2s)[idx] = __ldg(reinterpret_cast<const float4*>(g_Wt2) + idx);
    }
    __syncthreads();

    const int n0 = (tid & 31) * 4;
    const int o0 = (tid >> 5) * 8;
    float acc1[4][8], acc2[4][8];
    #pragma unroll
    for (int j = 0; j < 4; ++j)
        #pragma unroll
        for (int r = 0; r < 8; ++r){ acc1[j][r] = 0.f; acc2[j][r] = 0.f; }

    #pragma unroll 8
    for (int c = 0; c < CH; ++c){
        float4 a   = *reinterpret_cast<const float4*>(Xs  + c*128 + n0);
        float4 w10 = *reinterpret_cast<const float4*>(W1s + c*64 + o0);
        float4 w11 = *reinterpret_cast<const float4*>(W1s + c*64 + o0 + 4);
        float4 w20 = *reinterpret_cast<const float4*>(W2s + c*64 + o0);
        float4 w21 = *reinterpret_cast<const float4*>(W2s + c*64 + o0 + 4);
        float af[4]  = {a.x, a.y, a.z, a.w};
        float w1f[8] = {w10.x,w10.y,w10.z,w10.w,w11.x,w11.y,w11.z,w11.w};
        float w2f[8] = {w20.x,w20.y,w20.z,w20.w,w21.x,w21.y,w21.z,w21.w};
        #pragma unroll
        for (int j = 0; j < 4; ++j)
            #pragma unroll
            for (int r = 0; r < 8; ++r){
                acc1[j][r] = fmaf(af[j], w1f[r], acc1[j][r]);
                acc2[j][r] = fmaf(af[j], w2f[r], acc2[j][r]);
            }
    }

    #pragma unroll
    for (int j = 0; j < 4; ++j){
        int row = (b*NPTS + nbase + n0 + j)*NOUT + o0;
        *reinterpret_cast<float4*>(g_Y1 + row)     = make_float4(acc1[j][0],acc1[j][1],acc1[j][2],acc1[j][3]);
        *reinterpret_cast<float4*>(g_Y1 + row + 4) = make_float4(acc1[j][4],acc1[j][5],acc1[j][6],acc1[j][7]);
        *reinterpret_cast<float4*>(g_Y2 + row)     = make_float4(acc2[j][0],acc2[j][1],acc2[j][2],acc2[j][3]);
        *reinterpret_cast<float4*>(g_Y2 + row + 4) = make_float4(acc2[j][4],acc2[j][5],acc2[j][6],acc2[j][7]);
    }
}

// ---------------- kernel 3: gather neighbors, h stats, per-(n,o) max/min over k ----------------
__global__ void __launch_bounds__(256, 1) gather_kernel(){
    __shared__ float ssum[NOUT], ssum2[NOUT];
    const int tid = threadIdx.x;
    if (tid < NOUT){ ssum[tid] = 0.f; ssum2[tid] = 0.f; }
    __syncthreads();

    const int b = blockIdx.x >> 6;
    const int nbase = (blockIdx.x & 63) * 64;
    const int lane = tid & 31, wid = tid >> 5;
    const int half = lane >> 4;
    const int c4 = lane & 15;

    const float4* Y1f = reinterpret_cast<const float4*>(g_Y1);
    const float4* Y2f = reinterpret_cast<const float4*>(g_Y2);
    float4* hmaxf = reinterpret_cast<float4*>(g_hmax);
    float4* hminf = reinterpret_cast<float4*>(g_hmin);

    float a0=0.f, a1=0.f, a2=0.f, a3=0.f;
    float b0=0.f, b1=0.f, b2=0.f, b3=0.f;

    #pragma unroll 1
    for (int it = 0; it < 4; ++it){
        int np  = nbase + it*16 + wid*2;
        int bnp = b*NPTS + np;
        int ia = g_idx[ bnp   *KNN + lane];
        int ib = g_idx[(bnp+1)*KNN + lane];
        int bn = bnp + half;
        float4 y1 = __ldg(Y1f + bn*16 + c4);
        float4 mx = make_float4(-3.0e38f,-3.0e38f,-3.0e38f,-3.0e38f);
        float4 mn = make_float4( 3.0e38f, 3.0e38f, 3.0e38f, 3.0e38f);
        #pragma unroll
        for (int k = 0; k < KNN; ++k){
            int ma = __shfl_sync(0xffffffffu, ia, k);
            int mb = __shfl_sync(0xffffffffu, ib, k);
            int m  = half ? mb : ma;
            float4 y2 = __ldg(Y2f + (b*NPTS + m)*16 + c4);
            float h0 = y1.x + y2.x, h1 = y1.y + y2.y, h2 = y1.z + y2.z, h3 = y1.w + y2.w;
            a0 += h0; a1 += h1; a2 += h2; a3 += h3;
            b0 = fmaf(h0,h0,b0); b1 = fmaf(h1,h1,b1); b2 = fmaf(h2,h2,b2); b3 = fmaf(h3,h3,b3);
            mx.x = fmaxf(mx.x,h0); mx.y = fmaxf(mx.y,h1); mx.z = fmaxf(mx.z,h2); mx.w = fmaxf(mx.w,h3);
            mn.x = fminf(mn.x,h0); mn.y = fminf(mn.y,h1); mn.z = fminf(mn.z,h2); mn.w = fminf(mn.w,h3);
        }
        hmaxf[bn*16 + c4] = mx;
        hminf[bn*16 + c4] = mn;
    }

    atomicAdd(&ssum [c4*4+0], a0); atomicAdd(&ssum [c4*4+1], a1);
    atomicAdd(&ssum [c4*4+2], a2); atomicAdd(&ssum [c4*4+3], a3);
    atomicAdd(&ssum2[c4*4+0], b0); atomicAdd(&ssum2[c4*4+1], b1);
    atomicAdd(&ssum2[c4*4+2], b2); atomicAdd(&ssum2[c4*4+3], b3);
    __syncthreads();
    if (tid < NOUT){
        atomicAdd(&g_sum[tid],   ssum[tid]);
        atomicAdd(&g_sumsq[tid], ssum2[tid]);
    }
}

// ---------------- kernel 4: BN scale/shift ----------------
__global__ void finalize_kernel(const float* __restrict__ gamma,
                                const float* __restrict__ beta){
    int o = threadIdx.x;
    if (o < NOUT){
        const float inv = 1.f / (float)(BATCH*NPTS*KNN);
        float mean = g_sum[o] * inv;
        float var  = g_sumsq[o] * inv - mean*mean;
        float a = gamma[o] * rsqrtf(var + 1e-5f);
        g_a[o] = a;
        g_c[o] = beta[o] - a*mean;
    }
}

// ---------------- kernel 5: affine + relu + transpose to (B,O,N) ----------------
__global__ void __launch_bounds__(256, 1) output_kernel(float* __restrict__ out){
    __shared__ float smx[64][65];
    __shared__ float smn[64][65];
    const int tid = threadIdx.x;
    const int b = blockIdx.x >> 6;
    const int nbase = (blockIdx.x & 63) * 64;
    const float4* hmaxf = reinterpret_cast<const float4*>(g_hmax);
    const float4* hminf = reinterpret_cast<const float4*>(g_hmin);

    #pragma unroll
    for (int it = 0; it < 4; ++it){
        int idx = it*256 + tid;
        int r = idx >> 4, cc = idx & 15;
        float4 v = __ldg(hmaxf + (b*NPTS + nbase + r)*16 + cc);
        smx[r][cc*4+0] = v.x; smx[r][cc*4+1] = v.y; smx[r][cc*4+2] = v.z; smx[r][cc*4+3] = v.w;
        float4 w = __ldg(hminf + (b*NPTS + nbase + r)*16 + cc);
        smn[r][cc*4+0] = w.x; smn[r][cc*4+1] = w.y; smn[r][cc*4+2] = w.z; smn[r][cc*4+3] = w.w;
    }
    __syncthreads();

    #pragma unroll
    for (int it = 0; it < 16; ++it){
        int o  = it*4 + (tid >> 6);
        int nn = tid & 63;
        float a = g_a[o], c = g_c[o];
        float h = (a >= 0.f) ? smx[nn][o] : smn[nn][o];
        out[b*NOUT*NPTS + o*NPTS + nbase + nn] = fmaxf(fmaf(a, h, c), 0.f);
    }
}

// ---------------- launch ----------------
extern "C" void kernel_launch(void* const* d_in, const int* in_sizes, int n_in,
                              void* d_out, int out_size){
    const float* points = (const float*)d_in[0];   // (B, C, N)
    const float* W      = (const float*)d_in[1];   // (O, 2C)
    const float* gamma  = (const float*)d_in[2];   // (O,)
    const float* beta   = (const float*)d_in[3];   // (O,)
    float* out = (float*)d_out;                    // (B, O, N)

    const int KNN_SMEM = (64*64 + 64*128 + 4096) * 4;   // 65536 B
    cudaFuncSetAttribute((const void*)knn_kernel,
                         cudaFuncAttributeMaxDynamicSharedMemorySize, KNN_SMEM);
    cudaFuncSetAttribute((const void*)ygemm_kernel,
                         cudaFuncAttributeMaxDynamicSharedMemorySize, 64*1024);

    wprep_kernel   <<<16, 256>>>(W);
    sqnorm_kernel  <<<64, 256>>>(points);
    zero_kernel    <<<1, 64>>>();
    knn_kernel     <<<BATCH*(NPTS/64), 512, KNN_SMEM>>>(points);
    ygemm_kernel   <<<BATCH*(NPTS/128), 256, 64*1024>>>(points);
    gather_kernel  <<<BATCH*(NPTS/64), 256>>>();
    finalize_kernel<<<1, 64>>>(gamma, beta);
    output_kernel  <<<BATCH*(NPTS/64), 256>>>(out);
}